// round 4
// baseline (speedup 1.0000x reference)
#include <cuda_runtime.h>
#include <cuda_bf16.h>
#include <math.h>

// ---------------- problem constants ----------------
// B=16, Cmel=80, Ctxt=256, Catt=80, T1=800, T2=200
#define NB   16
#define T1D  800
#define T2D  200

// ---------------- scratch (no allocation allowed) ----------------
__device__ float g_k1[16 * 512 * 200];   // key conv1 output (relu)
__device__ float g_kk[16 * 80 * 200];    // key encoder output k
__device__ float g_q1[16 * 160 * 800];   // query conv1 output (relu)
__device__ float g_qm[16 * 80 * 800];    // query conv2 output (relu)
__device__ float g_qq[16 * 80 * 800];    // query encoder output q
__device__ float g_k2[16 * 200];         // ||k||^2 per (b,t2)
__device__ float g_q2[16 * 800];         // ||q||^2 per (b,t1)

// ---------------- k=3 conv (pad=1) + ReLU ----------------
// block: 128 threads = 16 co-groups x 8 t-groups. Block computes 32 co x TTILE t.
// thread: 2 co (co_l, co_l+16) x 25 consecutive t, sliding window over x.
template<int CIN, int CICHUNK, int TTILE>
__global__ __launch_bounds__(128)
void conv3_relu_kernel(const float* __restrict__ x, const float* __restrict__ w,
                       const float* __restrict__ bias, float* __restrict__ y,
                       int Cout, int T)
{
    constexpr int XSTR = TTILE + 2;            // padded row
    constexpr int WSTR = CICHUNK * 3 + 1;      // +1: kill 4-way bank conflict
    constexpr int JT   = TTILE / 8;            // 25
    __shared__ float xs[CICHUNK * XSTR];
    __shared__ float ws[32 * WSTR];

    const int b    = blockIdx.z;
    const int cb   = blockIdx.y;
    const int t0   = blockIdx.x * TTILE;
    const int tid  = threadIdx.x;
    const int co_l = tid >> 3;                 // 0..15
    const int tg   = tid & 7;
    const int toff = tg * JT;

    float acc0[JT], acc1[JT];
    #pragma unroll
    for (int j = 0; j < JT; ++j) { acc0[j] = 0.f; acc1[j] = 0.f; }

    const float* xb = x + (size_t)b * CIN * T;

    for (int cc = 0; cc < CIN / CICHUNK; ++cc) {
        for (int idx = tid; idx < CICHUNK * XSTR; idx += 128) {
            int jcol = idx % XSTR;
            int r    = idx / XSTR;
            int t    = t0 + jcol - 1;
            float v  = 0.f;
            if (t >= 0 && t < T) v = xb[(cc * CICHUNK + r) * T + t];
            xs[idx] = v;
        }
        for (int idx = tid; idx < 32 * CICHUNK * 3; idx += 128) {
            int r = idx / (CICHUNK * 3), s = idx % (CICHUNK * 3);
            ws[r * WSTR + s] = w[(size_t)(cb * 32 + r) * (CIN * 3) + cc * CICHUNK * 3 + s];
        }
        __syncthreads();

        for (int ci = 0; ci < CICHUNK; ++ci) {
            const float* wr0 = &ws[co_l * WSTR + ci * 3];
            const float* wr1 = &ws[(co_l + 16) * WSTR + ci * 3];
            float w00 = wr0[0], w01 = wr0[1], w02 = wr0[2];
            float w10 = wr1[0], w11 = wr1[1], w12 = wr1[2];
            const float* xr = &xs[ci * XSTR + toff];
            float a = xr[0], bb = xr[1];
            #pragma unroll
            for (int j = 0; j < JT; ++j) {
                float c = xr[2 + j];
                acc0[j] = fmaf(w00, a, acc0[j]);
                acc0[j] = fmaf(w01, bb, acc0[j]);
                acc0[j] = fmaf(w02, c, acc0[j]);
                acc1[j] = fmaf(w10, a, acc1[j]);
                acc1[j] = fmaf(w11, bb, acc1[j]);
                acc1[j] = fmaf(w12, c, acc1[j]);
                a = bb; bb = c;
            }
        }
        __syncthreads();
    }

    const int co0 = cb * 32 + co_l;
    const int co1 = co0 + 16;
    float b0 = bias[co0], b1 = bias[co1];
    float* y0 = y + ((size_t)b * Cout + co0) * T + t0 + toff;
    float* y1 = y + ((size_t)b * Cout + co1) * T + t0 + toff;
    #pragma unroll
    for (int j = 0; j < JT; ++j) {
        float v0 = acc0[j] + b0, v1 = acc1[j] + b1;
        y0[j] = v0 > 0.f ? v0 : 0.f;
        y1[j] = v1 > 0.f ? v1 : 0.f;
    }
}

// ---------------- 1x1 conv (GEMM) ----------------
// block: 256 threads = 8 warps. TTILE=64. thread: co = cb*COTILE + warp + 8*o (o<COTILE/8),
// t pair = t0 + lane*2 (float2 smem loads).
template<int CICHUNK, int COTILE, bool RELU>
__global__ __launch_bounds__(256)
void conv1x1_kernel(const float* __restrict__ x, const float* __restrict__ w,
                    const float* __restrict__ bias, float* __restrict__ y,
                    int Cin, int Cout, int T)
{
    constexpr int TT = 64;
    constexpr int NO = COTILE / 8;
    __shared__ float xs[CICHUNK * TT];
    __shared__ float ws[COTILE * CICHUNK];

    const int b    = blockIdx.z;
    const int cb   = blockIdx.y;
    const int t0   = blockIdx.x * TT;
    const int tid  = threadIdx.x;
    const int warp = tid >> 5;
    const int lane = tid & 31;

    float acc0[NO], acc1[NO];
    #pragma unroll
    for (int o = 0; o < NO; ++o) { acc0[o] = 0.f; acc1[o] = 0.f; }

    const float* xb = x + (size_t)b * Cin * T;

    for (int cc = 0; cc < Cin / CICHUNK; ++cc) {
        for (int idx = tid; idx < CICHUNK * TT; idx += 256) {
            int r = idx >> 6, c = idx & 63;
            int t = t0 + c;
            xs[idx] = (t < T) ? xb[(cc * CICHUNK + r) * T + t] : 0.f;
        }
        for (int idx = tid; idx < COTILE * CICHUNK; idx += 256) {
            int r = idx / CICHUNK, s = idx % CICHUNK;
            ws[idx] = w[(size_t)(cb * COTILE + r) * Cin + cc * CICHUNK + s];
        }
        __syncthreads();
        for (int ci = 0; ci < CICHUNK; ++ci) {
            float2 xv = *reinterpret_cast<const float2*>(&xs[ci * TT + lane * 2]);
            #pragma unroll
            for (int o = 0; o < NO; ++o) {
                float wv = ws[(warp + 8 * o) * CICHUNK + ci];
                acc0[o] = fmaf(wv, xv.x, acc0[o]);
                acc1[o] = fmaf(wv, xv.y, acc1[o]);
            }
        }
        __syncthreads();
    }

    int t = t0 + lane * 2;
    #pragma unroll
    for (int o = 0; o < NO; ++o) {
        int co = cb * COTILE + warp + 8 * o;
        float bv = bias[co];
        float v0 = acc0[o] + bv, v1 = acc1[o] + bv;
        if (RELU) { v0 = v0 > 0.f ? v0 : 0.f; v1 = v1 > 0.f ? v1 : 0.f; }
        float* yp = y + ((size_t)b * Cout + co) * T;
        if (t < T)     yp[t]     = v0;
        if (t + 1 < T) yp[t + 1] = v1;
    }
}

// ---------------- sum of squares over channels ----------------
__global__ void sumsq_kernel(const float* __restrict__ x, float* __restrict__ out,
                             int C, int T, int total)
{
    int idx = blockIdx.x * blockDim.x + threadIdx.x;
    if (idx >= total) return;
    int b = idx / T, t = idx % T;
    const float* p = x + (size_t)b * C * T + t;
    float s = 0.f;
    for (int c = 0; c < C; ++c) { float v = p[(size_t)c * T]; s = fmaf(v, v, s); }
    out[idx] = s;
}

// ---------------- logits = -5e-4 * (||q||^2 + ||k||^2 - 2 q.k) ----------------
// grid (25, 16): block covers 32 t1 x 200 t2. 128 threads: thread = 2 t1 x 25 t2.
__global__ __launch_bounds__(128)
void attn_logits_kernel(const float* __restrict__ q, const float* __restrict__ k,
                        const float* __restrict__ q2, const float* __restrict__ k2,
                        float* __restrict__ out)
{
    constexpr int C = 80;
    __shared__ float ks[40 * T2D];
    __shared__ float qs[32 * 81];
    __shared__ float k2s[T2D];

    const int b      = blockIdx.y;
    const int t1base = blockIdx.x * 32;
    const int tid    = threadIdx.x;
    const int t1l    = tid >> 3;       // 0..15
    const int t2g    = tid & 7;
    const int toff   = t2g * 25;

    float acc0[25], acc1[25];
    #pragma unroll
    for (int j = 0; j < 25; ++j) { acc0[j] = 0.f; acc1[j] = 0.f; }

    for (int idx = tid; idx < 32 * C; idx += 128) {
        int c = idx >> 5, r = idx & 31;   // coalesced over r
        qs[r * 81 + c] = q[((size_t)b * C + c) * T1D + t1base + r];
    }
    for (int idx = tid; idx < T2D; idx += 128) k2s[idx] = k2[b * T2D + idx];
    float q2v0 = q2[b * T1D + t1base + t1l];
    float q2v1 = q2[b * T1D + t1base + t1l + 16];

    for (int cc = 0; cc < 2; ++cc) {
        for (int idx = tid; idx < 40 * T2D; idx += 128) {
            ks[idx] = k[((size_t)b * C + cc * 40 + (idx / T2D)) * T2D + (idx % T2D)];
        }
        __syncthreads();
        for (int ci = 0; ci < 40; ++ci) {
            float qv0 = qs[t1l * 81 + cc * 40 + ci];
            float qv1 = qs[(t1l + 16) * 81 + cc * 40 + ci];
            const float* kr = &ks[ci * T2D + toff];
            #pragma unroll
            for (int j = 0; j < 25; ++j) {
                float kv = kr[j];
                acc0[j] = fmaf(qv0, kv, acc0[j]);
                acc1[j] = fmaf(qv1, kv, acc1[j]);
            }
        }
        __syncthreads();
    }

    const int t1a = t1base + t1l;
    float* o0 = out + ((size_t)b * T1D + t1a) * T2D + toff;
    float* o1 = out + ((size_t)b * T1D + t1a + 16) * T2D + toff;
    #pragma unroll
    for (int j = 0; j < 25; ++j) {
        float kk = k2s[toff + j];
        o0[j] = -0.0005f * (q2v0 + kk - 2.f * acc0[j]);
        o1[j] = -0.0005f * (q2v1 + kk - 2.f * acc1[j]);
    }
}

// ---------------- in-place log_softmax over t2 + log(prior + 1e-8) ----------------
// one warp per (b,t1) row of 200.
__global__ __launch_bounds__(256)
void softmax_prior_kernel(float* __restrict__ out, const float* __restrict__ prior)
{
    int row  = blockIdx.x * 8 + (threadIdx.x >> 5);
    int lane = threadIdx.x & 31;
    float* p = out + (size_t)row * T2D;
    const float* pr = prior + (size_t)row * T2D;

    float v[7];
    float m = -1e30f;
    #pragma unroll
    for (int kk = 0; kk < 7; ++kk) {
        int i = lane + kk * 32;
        v[kk] = (i < T2D) ? p[i] : -1e30f;
        m = fmaxf(m, v[kk]);
    }
    #pragma unroll
    for (int off = 16; off; off >>= 1) m = fmaxf(m, __shfl_xor_sync(0xffffffff, m, off));
    float s = 0.f;
    #pragma unroll
    for (int kk = 0; kk < 7; ++kk) s += expf(v[kk] - m);
    #pragma unroll
    for (int off = 16; off; off >>= 1) s += __shfl_xor_sync(0xffffffff, s, off);
    float L = m + logf(s);
    #pragma unroll
    for (int kk = 0; kk < 7; ++kk) {
        int i = lane + kk * 32;
        if (i < T2D) p[i] = v[kk] - L + logf(pr[i] + 1e-8f);
    }
}

// ---------------- launch ----------------
extern "C" void kernel_launch(void* const* d_in, const int* in_sizes, int n_in,
                              void* d_out, int out_size)
{
    const float* queries = (const float*)d_in[0];   // (16,80,800)
    const float* keys    = (const float*)d_in[1];   // (16,256,200)
    const float* prior   = (const float*)d_in[2];   // (16,800,200)
    const float* kw1     = (const float*)d_in[3];   // (512,256,3)
    const float* kb1     = (const float*)d_in[4];
    const float* kw2     = (const float*)d_in[5];   // (80,512,1)
    const float* kb2     = (const float*)d_in[6];
    const float* qw1     = (const float*)d_in[7];   // (160,80,3)
    const float* qb1     = (const float*)d_in[8];
    const float* qw2     = (const float*)d_in[9];   // (80,160,1)
    const float* qb2     = (const float*)d_in[10];
    const float* qw3     = (const float*)d_in[11];  // (80,80,1)
    const float* qb3     = (const float*)d_in[12];
    float* out = (float*)d_out;

    float *k1p, *kkp, *q1p, *qmp, *qqp, *k2p, *q2p;
    cudaGetSymbolAddress((void**)&k1p, g_k1);
    cudaGetSymbolAddress((void**)&kkp, g_kk);
    cudaGetSymbolAddress((void**)&q1p, g_q1);
    cudaGetSymbolAddress((void**)&qmp, g_qm);
    cudaGetSymbolAddress((void**)&qqp, g_qq);
    cudaGetSymbolAddress((void**)&k2p, g_k2);
    cudaGetSymbolAddress((void**)&q2p, g_q2);

    // key encoder
    conv3_relu_kernel<256, 32, 200><<<dim3(1, 16, NB), 128>>>(keys, kw1, kb1, k1p, 512, T2D);
    conv1x1_kernel<64, 40, false><<<dim3(4, 2, NB), 256>>>(k1p, kw2, kb2, kkp, 512, 80, T2D);
    sumsq_kernel<<<(NB * T2D + 255) / 256, 256>>>(kkp, k2p, 80, T2D, NB * T2D);

    // query encoder
    conv3_relu_kernel<80, 16, 200><<<dim3(4, 5, NB), 128>>>(queries, qw1, qb1, q1p, 160, T1D);
    conv1x1_kernel<32, 40, true><<<dim3(13, 2, NB), 256>>>(q1p, qw2, qb2, qmp, 160, 80, T1D);
    conv1x1_kernel<16, 40, false><<<dim3(13, 2, NB), 256>>>(qmp, qw3, qb3, qqp, 80, 80, T1D);
    sumsq_kernel<<<(NB * T1D + 255) / 256, 256>>>(qqp, q2p, 80, T1D, NB * T1D);

    // attention logits + log_softmax + prior
    attn_logits_kernel<<<dim3(25, NB), 128>>>(qqp, kkp, q2p, k2p, out);
    softmax_prior_kernel<<<NB * T1D / 8, 256>>>(out, prior);
}

// round 5
// speedup vs baseline: 1.0073x; 1.0073x over previous
#include <cuda_runtime.h>
#include <cuda_bf16.h>
#include <math.h>

// ---------------- problem constants ----------------
// B=16, Cmel=80, Ctxt=256, Catt=80, T1=800, T2=200
#define NB   16
#define T1D  800
#define T2D  200

typedef unsigned long long ull;

// ---------------- f32x2 packed math (PTX-only on sm_103a) ----------------
__device__ __forceinline__ ull pk2(float lo, float hi) {
    ull r; asm("mov.b64 %0, {%1,%2};" : "=l"(r) : "f"(lo), "f"(hi)); return r;
}
__device__ __forceinline__ ull bcast2(float v) { return pk2(v, v); }
__device__ __forceinline__ ull ffma2(ull a, ull b, ull c) {
    ull d; asm("fma.rn.f32x2 %0, %1, %2, %3;" : "=l"(d) : "l"(a), "l"(b), "l"(c)); return d;
}
__device__ __forceinline__ float2 unpk(ull v) {
    float2 f; asm("mov.b64 {%0,%1}, %2;" : "=f"(f.x), "=f"(f.y) : "l"(v)); return f;
}

// ---------------- scratch (no allocation allowed) ----------------
__device__ float g_k1[16 * 512 * 200];   // key conv1 output (relu)
__device__ float g_kk[16 * 80 * 200];    // key encoder output k
__device__ float g_q1[16 * 160 * 800];   // query conv1 output (relu)
__device__ float g_qm[16 * 80 * 800];    // query conv2 output (relu)
__device__ float g_qq[16 * 80 * 800];    // query encoder output q
__device__ float g_k2[16 * 200];         // ||k||^2 per (b,t2)
__device__ float g_q2[16 * 800];         // ||q||^2 per (b,t1)

// ---------------- k=3 conv (pad=1) + ReLU, f32x2 packed over co ----------------
// block: 128 threads = 8 co-lanes x 16 t-groups. Block computes 32 co x TTILE t.
// thread: 4 co (co_l*4 + {0..3}) as 2 packed pairs, JT consecutive t each.
// Weights stored PRE-PAIRED in smem: one LDS.64 = one (co even, co odd) pair.
template<int CIN, int CICHUNK, int JT>
__global__ __launch_bounds__(128)
void conv3_relu_f2_kernel(const float* __restrict__ x, const float* __restrict__ w,
                          const float* __restrict__ bias, float* __restrict__ y,
                          int Cout, int T)
{
    constexpr int TTILE = 16 * JT;
    constexpr int XSTR  = TTILE + 2;
    constexpr int PSTR  = 6 * CICHUNK + 2;   // floats per co-pair row (even, padded)
    __shared__ float xs[CICHUNK * XSTR];
    __shared__ float ws[16 * PSTR];          // 16 co-pairs

    const int b    = blockIdx.z;
    const int cb   = blockIdx.y;
    const int t0   = blockIdx.x * TTILE;
    const int tid  = threadIdx.x;
    const int co_l = tid & 7;                // 0..7
    const int tg   = tid >> 3;               // 0..15
    const int toff = tg * JT;

    ull acc0[JT], acc1[JT];
    #pragma unroll
    for (int j = 0; j < JT; ++j) { acc0[j] = 0ull; acc1[j] = 0ull; }

    const float* xb = x + (size_t)b * CIN * T;

    for (int cc = 0; cc < CIN / CICHUNK; ++cc) {
        // stage x (zero-padded at both edges / tail)
        for (int idx = tid; idx < CICHUNK * XSTR; idx += 128) {
            int jcol = idx % XSTR;
            int r    = idx / XSTR;
            int t    = t0 + jcol - 1;
            float v  = 0.f;
            if (t >= 0 && t < T) v = xb[(cc * CICHUNK + r) * T + t];
            xs[idx] = v;
        }
        // stage weights pre-paired: pair p holds co (2p, 2p+1) interleaved per (ci,s)
        for (int idx = tid; idx < 32 * CICHUNK * 3; idx += 128) {
            int r = idx / (CICHUNK * 3), s = idx % (CICHUNK * 3);
            ws[(r >> 1) * PSTR + s * 2 + (r & 1)] =
                w[(size_t)(cb * 32 + r) * (CIN * 3) + cc * CICHUNK * 3 + s];
        }
        __syncthreads();

        const int p0 = co_l * 2, p1 = co_l * 2 + 1;
        #pragma unroll 2
        for (int ci = 0; ci < CICHUNK; ++ci) {
            const ull* w0 = (const ull*)&ws[p0 * PSTR + ci * 6];
            const ull* w1 = (const ull*)&ws[p1 * PSTR + ci * 6];
            ull wa0 = w0[0], wb0 = w0[1], wc0 = w0[2];
            ull wa1 = w1[0], wb1 = w1[1], wc1 = w1[2];
            const float* xr = &xs[ci * XSTR + toff];
            ull pa = bcast2(xr[0]), pb = bcast2(xr[1]);
            #pragma unroll
            for (int j = 0; j < JT; ++j) {
                ull pc = bcast2(xr[2 + j]);
                acc0[j] = ffma2(wa0, pa, acc0[j]);
                acc0[j] = ffma2(wb0, pb, acc0[j]);
                acc0[j] = ffma2(wc0, pc, acc0[j]);
                acc1[j] = ffma2(wa1, pa, acc1[j]);
                acc1[j] = ffma2(wb1, pb, acc1[j]);
                acc1[j] = ffma2(wc1, pc, acc1[j]);
                pa = pb; pb = pc;
            }
        }
        __syncthreads();
    }

    // epilogue: 4 co per thread = pairs (co0,co0+1) and (co0+2,co0+3)
    const int co0 = cb * 32 + co_l * 4;
    float b0 = bias[co0], b1 = bias[co0 + 1], b2 = bias[co0 + 2], b3 = bias[co0 + 3];
    float* yr = y + ((size_t)b * Cout + co0) * T;
    #pragma unroll
    for (int j = 0; j < JT; ++j) {
        int t = t0 + toff + j;
        if (t < T) {
            float2 v0 = unpk(acc0[j]);
            float2 v1 = unpk(acc1[j]);
            float r0 = v0.x + b0, r1 = v0.y + b1, r2 = v1.x + b2, r3 = v1.y + b3;
            yr[t]             = r0 > 0.f ? r0 : 0.f;
            yr[(size_t)T + t] = r1 > 0.f ? r1 : 0.f;
            yr[(size_t)2*T + t] = r2 > 0.f ? r2 : 0.f;
            yr[(size_t)3*T + t] = r3 > 0.f ? r3 : 0.f;
        }
    }
}

// ---------------- 1x1 conv (GEMM), f32x2 packed over t ----------------
// block: 256 threads = 8 warps. TT=128 t per block; lane owns 2 float2 (t pairs
// at lane*2 and 64+lane*2). warp+8o selects co. Weights pre-duplicated in smem.
template<int CICHUNK, int COTILE, bool RELU>
__global__ __launch_bounds__(256)
void conv1x1_f2_kernel(const float* __restrict__ x, const float* __restrict__ w,
                       const float* __restrict__ bias, float* __restrict__ y,
                       int Cin, int Cout, int T)
{
    constexpr int TT = 128;
    constexpr int NO = COTILE / 8;
    __shared__ float xs[CICHUNK * TT];
    __shared__ ull   wsd[COTILE * CICHUNK];   // (w,w) duplicated pairs

    const int b    = blockIdx.z;
    const int cb   = blockIdx.y;
    const int t0   = blockIdx.x * TT;
    const int tid  = threadIdx.x;
    const int warp = tid >> 5;
    const int lane = tid & 31;

    ull acc0[NO], acc1[NO];
    #pragma unroll
    for (int o = 0; o < NO; ++o) { acc0[o] = 0ull; acc1[o] = 0ull; }

    const float* xb = x + (size_t)b * Cin * T;

    for (int cc = 0; cc < Cin / CICHUNK; ++cc) {
        for (int idx = tid; idx < CICHUNK * TT; idx += 256) {
            int r = idx >> 7, c = idx & 127;
            int t = t0 + c;
            xs[idx] = (t < T) ? xb[(cc * CICHUNK + r) * T + t] : 0.f;
        }
        for (int idx = tid; idx < COTILE * CICHUNK; idx += 256) {
            int r = idx / CICHUNK, s = idx % CICHUNK;
            float v = w[(size_t)(cb * COTILE + r) * Cin + cc * CICHUNK + s];
            wsd[idx] = pk2(v, v);
        }
        __syncthreads();
        #pragma unroll 4
        for (int ci = 0; ci < CICHUNK; ++ci) {
            ull xv0 = *(const ull*)&xs[ci * TT + lane * 2];
            ull xv1 = *(const ull*)&xs[ci * TT + 64 + lane * 2];
            #pragma unroll
            for (int o = 0; o < NO; ++o) {
                ull wv = wsd[(warp + 8 * o) * CICHUNK + ci];
                acc0[o] = ffma2(wv, xv0, acc0[o]);
                acc1[o] = ffma2(wv, xv1, acc1[o]);
            }
        }
        __syncthreads();
    }

    #pragma unroll
    for (int o = 0; o < NO; ++o) {
        int co = cb * COTILE + warp + 8 * o;
        float bv = bias[co];
        float* yp = y + ((size_t)b * Cout + co) * T;
        float2 v0 = unpk(acc0[o]);
        float2 v1 = unpk(acc1[o]);
        float a0 = v0.x + bv, a1 = v0.y + bv, a2 = v1.x + bv, a3 = v1.y + bv;
        if (RELU) {
            a0 = a0 > 0.f ? a0 : 0.f; a1 = a1 > 0.f ? a1 : 0.f;
            a2 = a2 > 0.f ? a2 : 0.f; a3 = a3 > 0.f ? a3 : 0.f;
        }
        int ta = t0 + lane * 2, tb = t0 + 64 + lane * 2;
        if (ta < T)     yp[ta]     = a0;
        if (ta + 1 < T) yp[ta + 1] = a1;
        if (tb < T)     yp[tb]     = a2;
        if (tb + 1 < T) yp[tb + 1] = a3;
    }
}

// ---------------- sum of squares over channels ----------------
__global__ void sumsq_kernel(const float* __restrict__ x, float* __restrict__ out,
                             int C, int T, int total)
{
    int idx = blockIdx.x * blockDim.x + threadIdx.x;
    if (idx >= total) return;
    int b = idx / T, t = idx % T;
    const float* p = x + (size_t)b * C * T + t;
    float s = 0.f;
    for (int c = 0; c < C; ++c) { float v = p[(size_t)c * T]; s = fmaf(v, v, s); }
    out[idx] = s;
}

// ---------------- logits = -5e-4 * (||q||^2 + ||k||^2 - 2 q.k) ----------------
// grid (25, 16): block covers 32 t1 x 200 t2. 128 threads: thread = 2 t1 x 25 t2.
__global__ __launch_bounds__(128)
void attn_logits_kernel(const float* __restrict__ q, const float* __restrict__ k,
                        const float* __restrict__ q2, const float* __restrict__ k2,
                        float* __restrict__ out)
{
    constexpr int C = 80;
    __shared__ float ks[40 * T2D];
    __shared__ float qs[32 * 81];
    __shared__ float k2s[T2D];

    const int b      = blockIdx.y;
    const int t1base = blockIdx.x * 32;
    const int tid    = threadIdx.x;
    const int t1l    = tid >> 3;       // 0..15
    const int t2g    = tid & 7;
    const int toff   = t2g * 25;

    float acc0[25], acc1[25];
    #pragma unroll
    for (int j = 0; j < 25; ++j) { acc0[j] = 0.f; acc1[j] = 0.f; }

    for (int idx = tid; idx < 32 * C; idx += 128) {
        int c = idx >> 5, r = idx & 31;   // coalesced over r
        qs[r * 81 + c] = q[((size_t)b * C + c) * T1D + t1base + r];
    }
    for (int idx = tid; idx < T2D; idx += 128) k2s[idx] = k2[b * T2D + idx];
    float q2v0 = q2[b * T1D + t1base + t1l];
    float q2v1 = q2[b * T1D + t1base + t1l + 16];

    for (int cc = 0; cc < 2; ++cc) {
        for (int idx = tid; idx < 40 * T2D; idx += 128) {
            ks[idx] = k[((size_t)b * C + cc * 40 + (idx / T2D)) * T2D + (idx % T2D)];
        }
        __syncthreads();
        for (int ci = 0; ci < 40; ++ci) {
            float qv0 = qs[t1l * 81 + cc * 40 + ci];
            float qv1 = qs[(t1l + 16) * 81 + cc * 40 + ci];
            const float* kr = &ks[ci * T2D + toff];
            #pragma unroll
            for (int j = 0; j < 25; ++j) {
                float kv = kr[j];
                acc0[j] = fmaf(qv0, kv, acc0[j]);
                acc1[j] = fmaf(qv1, kv, acc1[j]);
            }
        }
        __syncthreads();
    }

    const int t1a = t1base + t1l;
    float* o0 = out + ((size_t)b * T1D + t1a) * T2D + toff;
    float* o1 = out + ((size_t)b * T1D + t1a + 16) * T2D + toff;
    #pragma unroll
    for (int j = 0; j < 25; ++j) {
        float kk = k2s[toff + j];
        o0[j] = -0.0005f * (q2v0 + kk - 2.f * acc0[j]);
        o1[j] = -0.0005f * (q2v1 + kk - 2.f * acc1[j]);
    }
}

// ---------------- in-place log_softmax over t2 + log(prior + 1e-8) ----------------
// one warp per (b,t1) row of 200.
__global__ __launch_bounds__(256)
void softmax_prior_kernel(float* __restrict__ out, const float* __restrict__ prior)
{
    int row  = blockIdx.x * 8 + (threadIdx.x >> 5);
    int lane = threadIdx.x & 31;
    float* p = out + (size_t)row * T2D;
    const float* pr = prior + (size_t)row * T2D;

    float v[7];
    float m = -1e30f;
    #pragma unroll
    for (int kk = 0; kk < 7; ++kk) {
        int i = lane + kk * 32;
        v[kk] = (i < T2D) ? p[i] : -1e30f;
        m = fmaxf(m, v[kk]);
    }
    #pragma unroll
    for (int off = 16; off; off >>= 1) m = fmaxf(m, __shfl_xor_sync(0xffffffff, m, off));
    float s = 0.f;
    #pragma unroll
    for (int kk = 0; kk < 7; ++kk) s += expf(v[kk] - m);
    #pragma unroll
    for (int off = 16; off; off >>= 1) s += __shfl_xor_sync(0xffffffff, s, off);
    float L = m + logf(s);
    #pragma unroll
    for (int kk = 0; kk < 7; ++kk) {
        int i = lane + kk * 32;
        if (i < T2D) p[i] = v[kk] - L + logf(pr[i] + 1e-8f);
    }
}

// ---------------- launch ----------------
extern "C" void kernel_launch(void* const* d_in, const int* in_sizes, int n_in,
                              void* d_out, int out_size)
{
    const float* queries = (const float*)d_in[0];   // (16,80,800)
    const float* keys    = (const float*)d_in[1];   // (16,256,200)
    const float* prior   = (const float*)d_in[2];   // (16,800,200)
    const float* kw1     = (const float*)d_in[3];   // (512,256,3)
    const float* kb1     = (const float*)d_in[4];
    const float* kw2     = (const float*)d_in[5];   // (80,512,1)
    const float* kb2     = (const float*)d_in[6];
    const float* qw1     = (const float*)d_in[7];   // (160,80,3)
    const float* qb1     = (const float*)d_in[8];
    const float* qw2     = (const float*)d_in[9];   // (80,160,1)
    const float* qb2     = (const float*)d_in[10];
    const float* qw3     = (const float*)d_in[11];  // (80,80,1)
    const float* qb3     = (const float*)d_in[12];
    float* out = (float*)d_out;

    float *k1p, *kkp, *q1p, *qmp, *qqp, *k2p, *q2p;
    cudaGetSymbolAddress((void**)&k1p, g_k1);
    cudaGetSymbolAddress((void**)&kkp, g_kk);
    cudaGetSymbolAddress((void**)&q1p, g_q1);
    cudaGetSymbolAddress((void**)&qmp, g_qm);
    cudaGetSymbolAddress((void**)&qqp, g_qq);
    cudaGetSymbolAddress((void**)&k2p, g_k2);
    cudaGetSymbolAddress((void**)&q2p, g_q2);

    // key encoder: 256->512 k3 (TTILE=112, grid 2x16x16=512 blocks), then 1x1 512->80
    conv3_relu_f2_kernel<256, 32, 7><<<dim3(2, 16, NB), 128>>>(keys, kw1, kb1, k1p, 512, T2D);
    conv1x1_f2_kernel<64, 40, false><<<dim3(2, 2, NB), 256>>>(k1p, kw2, kb2, kkp, 512, 80, T2D);
    sumsq_kernel<<<(NB * T2D + 255) / 256, 256>>>(kkp, k2p, 80, T2D, NB * T2D);

    // query encoder: 80->160 k3 (TTILE=160, grid 5x5x16=400), 160->80 1x1, 80->80 1x1
    conv3_relu_f2_kernel<80, 16, 10><<<dim3(5, 5, NB), 128>>>(queries, qw1, qb1, q1p, 160, T1D);
    conv1x1_f2_kernel<32, 40, true><<<dim3(7, 2, NB), 256>>>(q1p, qw2, qb2, qmp, 160, 80, T1D);
    conv1x1_f2_kernel<16, 40, false><<<dim3(7, 2, NB), 256>>>(qmp, qw3, qb3, qqp, 80, 80, T1D);
    sumsq_kernel<<<(NB * T1D + 255) / 256, 256>>>(qqp, q2p, 80, T1D, NB * T1D);

    // attention logits + log_softmax + prior
    attn_logits_kernel<<<dim3(25, NB), 128>>>(qqp, kkp, q2p, k2p, out);
    softmax_prior_kernel<<<NB * T1D / 8, 256>>>(out, prior);
}